// round 3
// baseline (speedup 1.0000x reference)
#include <cuda_runtime.h>

#define NBATCH   128
#define N_ATOMS  4096
#define NB       4095
#define NA       4094
#define NT       4093
#define MAX_LEN  (5 * NT)   /* 20465 */
#define ROW      9
#define EPS      1e-8f

#define NTHREADS 1024

// shared layout
#define SM_BT     30
#define SM_AT     26
#define SM_TT     50
#define SM_MU     25
#define SM_RED    (3 * 32)
#define SMEM_TAIL_FLOATS (SM_BT + SM_AT + SM_TT + SM_MU + SM_RED)
#define SMEM_BYTES  (N_ATOMS * 16 + SMEM_TAIL_FLOATS * 4)

__global__ __launch_bounds__(NTHREADS, 1)
void local_energy_kernel(const float* __restrict__ feats,
                         const float* __restrict__ bond_type,
                         const float* __restrict__ angle_type,
                         const float* __restrict__ tor_type,
                         const int*   __restrict__ multiplicity,
                         const float* __restrict__ opt_pars,
                         float* __restrict__ out)
{
    extern __shared__ float4 smem4[];
    float4* sc4 = smem4;                        // [N_ATOMS] padded coords
    float*  tail = (float*)(smem4 + N_ATOMS);
    float* sbt  = tail;                          // bond_type [15][2]
    float* sat  = sbt + SM_BT;                   // angle_type [13][2]
    float* stt  = sat + SM_AT;                   // tor_type [25][2]
    float* smu  = stt + SM_TT;                   // multiplicity as float [25]
    float* sred = smu + SM_MU;                   // reduction scratch 3*32

    const int b   = blockIdx.x;
    const int tid = threadIdx.x;
    const float* f = feats + (size_t)b * MAX_LEN * ROW;

    // ---- stage coords: each thread loads 4 atoms (12 strided LDGs, MLP=12) ----
    {
        float cx[4], cy[4], cz[4];
        #pragma unroll
        for (int u = 0; u < 4; u++) {
            int a = tid + u * NTHREADS;
            const float* p = f + (size_t)(3 * a) * ROW + 5;
            cx[u] = p[0];
            cy[u] = p[ROW];
            cz[u] = p[2 * ROW];
        }
        #pragma unroll
        for (int u = 0; u < 4; u++) {
            int a = tid + u * NTHREADS;
            sc4[a] = make_float4(cx[u], cy[u], cz[u], 0.0f);
        }
    }

    if (tid < SM_BT) sbt[tid] = bond_type[tid];
    else if (tid < SM_BT + SM_AT) sat[tid - SM_BT] = angle_type[tid - SM_BT];
    else if (tid < SM_BT + SM_AT + SM_TT) stt[tid - SM_BT - SM_AT] = tor_type[tid - SM_BT - SM_AT];
    else if (tid < SM_BT + SM_AT + SM_TT + SM_MU)
        smu[tid - SM_BT - SM_AT - SM_TT] = (float)multiplicity[tid - SM_BT - SM_AT - SM_TT];
    __syncthreads();

    float eb = 0.0f, ea = 0.0f, et = 0.0f;

    // ---------------- bonds: batch all 12 index loads, then compute ----------------
    {
        float i0[4], i1[4], bt[4];
        #pragma unroll
        for (int u = 0; u < 4; u++) {
            int e = tid + u * NTHREADS;
            if (e < NB) {
                const float* fr = f + (size_t)(3 * e) * ROW + 6;
                i0[u] = fr[0]; i1[u] = fr[ROW]; bt[u] = fr[2 * ROW];
            } else { i0[u] = 0.0f; i1[u] = 0.0f; bt[u] = 0.0f; }
        }
        #pragma unroll
        for (int u = 0; u < 4; u++) {
            int e = tid + u * NTHREADS;
            if (e < NB) {
                float4 p0 = sc4[(int)i0[u]];
                float4 p1 = sc4[(int)i1[u]];
                int t = (int)bt[u];
                float dx = p0.x - p1.x, dy = p0.y - p1.y, dz = p0.z - p1.z;
                float r  = sqrtf(dx * dx + dy * dy + dz * dz + EPS);
                float dr = r - sbt[2 * t + 1];
                eb += sbt[2 * t + 0] * dr * dr;
            }
        }
    }

    // ---------------- angles: batch all 16 index loads ----------------
    {
        float a0[4], a1[4], a2[4], at[4];
        #pragma unroll
        for (int u = 0; u < 4; u++) {
            int e = tid + u * NTHREADS;
            if (e < NA) {
                const float* fr = f + (size_t)(4 * e) * ROW + 7;
                a0[u] = fr[0]; a1[u] = fr[ROW]; a2[u] = fr[2 * ROW]; at[u] = fr[3 * ROW];
            } else { a0[u] = 0.0f; a1[u] = 0.0f; a2[u] = 0.0f; at[u] = 0.0f; }
        }
        #pragma unroll
        for (int u = 0; u < 4; u++) {
            int e = tid + u * NTHREADS;
            if (e < NA) {
                float4 p0 = sc4[(int)a0[u]];
                float4 p1 = sc4[(int)a1[u]];
                float4 p2 = sc4[(int)a2[u]];
                int t = (int)at[u];
                float v1x = p0.x - p1.x, v1y = p0.y - p1.y, v1z = p0.z - p1.z;
                float v2x = p2.x - p1.x, v2y = p2.y - p1.y, v2z = p2.z - p1.z;
                float d11 = v1x * v1x + v1y * v1y + v1z * v1z + EPS;
                float d22 = v2x * v2x + v2y * v2y + v2z * v2z + EPS;
                float d12 = v1x * v2x + v1y * v2y + v1z * v2z;
                float cosang = d12 / (sqrtf(d11) * sqrtf(d22));
                cosang = fminf(fmaxf(cosang, -1.0f + 1e-6f), 1.0f - 1e-6f);
                float theta = acosf(cosang);
                float dt = theta - sat[2 * t + 1];
                ea += sat[2 * t + 0] * dt * dt;
            }
        }
    }

    // ---------------- torsions: 2 batches of 2 (10 LDGs each) ----------------
    #pragma unroll
    for (int half = 0; half < 2; half++) {
        float ti[2], tj[2], tk[2], tl[2], tt[2];
        #pragma unroll
        for (int u = 0; u < 2; u++) {
            int e = tid + (2 * half + u) * NTHREADS;
            if (e < NT) {
                const float* fr = f + (size_t)(5 * e) * ROW + 8;
                ti[u] = fr[0]; tj[u] = fr[ROW]; tk[u] = fr[2 * ROW];
                tl[u] = fr[3 * ROW]; tt[u] = fr[4 * ROW];
            } else { ti[u] = 0.0f; tj[u] = 0.0f; tk[u] = 0.0f; tl[u] = 0.0f; tt[u] = 0.0f; }
        }
        #pragma unroll
        for (int u = 0; u < 2; u++) {
            int e = tid + (2 * half + u) * NTHREADS;
            if (e < NT) {
                float4 pi = sc4[(int)ti[u]];
                float4 pj = sc4[(int)tj[u]];
                float4 pk = sc4[(int)tk[u]];
                float4 pl = sc4[(int)tl[u]];
                int t = (int)tt[u];

                float b1x = pj.x - pi.x, b1y = pj.y - pi.y, b1z = pj.z - pi.z;
                float b2x = pk.x - pj.x, b2y = pk.y - pj.y, b2z = pk.z - pj.z;
                float b3x = pl.x - pk.x, b3y = pl.y - pk.y, b3z = pl.z - pk.z;

                float n1x = b1y * b2z - b1z * b2y;
                float n1y = b1z * b2x - b1x * b2z;
                float n1z = b1x * b2y - b1y * b2x;
                float n2x = b2y * b3z - b2z * b3y;
                float n2y = b2z * b3x - b2x * b3z;
                float n2z = b2x * b3y - b2y * b3x;

                float inv = 1.0f / sqrtf(b2x * b2x + b2y * b2y + b2z * b2z + EPS);
                float bnx = b2x * inv, bny = b2y * inv, bnz = b2z * inv;

                float m1x = n1y * bnz - n1z * bny;
                float m1y = n1z * bnx - n1x * bnz;
                float m1z = n1x * bny - n1y * bnx;

                float y = m1x * n2x + m1y * n2y + m1z * n2z;
                float x = n1x * n2x + n1y * n2y + n1z * n2z;
                float phi = atan2f(y, x);

                et += stt[2 * t + 0] * (1.0f + cosf(smu[t] * phi - stt[2 * t + 1]));
            }
        }
    }

    // ---------------- block reduction ----------------
    const unsigned FULL = 0xFFFFFFFFu;
    #pragma unroll
    for (int off = 16; off > 0; off >>= 1) {
        eb += __shfl_down_sync(FULL, eb, off);
        ea += __shfl_down_sync(FULL, ea, off);
        et += __shfl_down_sync(FULL, et, off);
    }
    int warp = tid >> 5;
    int lane = tid & 31;
    if (lane == 0) {
        sred[warp]      = eb;
        sred[32 + warp] = ea;
        sred[64 + warp] = et;
    }
    __syncthreads();
    if (warp == 0) {
        float vb = sred[lane];
        float va = sred[32 + lane];
        float vt = sred[64 + lane];
        #pragma unroll
        for (int off = 16; off > 0; off >>= 1) {
            vb += __shfl_down_sync(FULL, vb, off);
            va += __shfl_down_sync(FULL, va, off);
            vt += __shfl_down_sync(FULL, vt, off);
        }
        if (lane == 0) {
            out[3 * b + 0] = opt_pars[0] * vb;
            out[3 * b + 1] = opt_pars[1] * va;
            out[3 * b + 2] = opt_pars[2] * vt;
        }
    }
}

extern "C" void kernel_launch(void* const* d_in, const int* in_sizes, int n_in,
                              void* d_out, int out_size)
{
    const float* feats      = (const float*)d_in[0];
    /* d_in[1] = lengths (unused by reference) */
    const float* bond_type  = (const float*)d_in[2];
    const float* angle_type = (const float*)d_in[3];
    const float* tor_type   = (const float*)d_in[4];
    const int*   mult       = (const int*)  d_in[5];
    const float* opt_pars   = (const float*)d_in[6];
    float*       out        = (float*)d_out;

    cudaFuncSetAttribute(local_energy_kernel,
                         cudaFuncAttributeMaxDynamicSharedMemorySize, SMEM_BYTES);

    local_energy_kernel<<<NBATCH, NTHREADS, SMEM_BYTES>>>(
        feats, bond_type, angle_type, tor_type, mult, opt_pars, out);
}

// round 4
// speedup vs baseline: 1.0362x; 1.0362x over previous
#include <cuda_runtime.h>

#define NBATCH   128
#define N_ATOMS  4096
#define NB       4095
#define NA       4094
#define NT       4093
#define MAX_LEN  (5 * NT)            /* 20465 rows */
#define ROW      9
#define TOT_F    (MAX_LEN * ROW)     /* 184185 floats per sample */
#define EPS      1e-8f

#define NTHREADS 1024
#define TILE_ROWS 1024
#define TILE_F    (TILE_ROWS * ROW)  /* 9216 */
#define NTILES    ((MAX_LEN + TILE_ROWS - 1) / TILE_ROWS)  /* 20 */

/* ---- shared memory layout (bytes) ---- */
#define OFF_SC4    0                         /* float4 coords[4096]      65536 */
#define OFF_STAGE  65536                     /* float staging[9224]      36896 */
#define OFF_SB16   102432                    /* u16 bonds[12288]         24576 */
#define OFF_SA16   127008                    /* u16 angles[16376]        32752 */
#define OFF_SG16   159760                    /* u16 tors[20466]          40932 */
#define OFF_TBL    200704                    /* float tables[227]          908 */
#define SMEM_BYTES 201616

#define SM_BT 30
#define SM_AT 26
#define SM_TT 50
#define SM_MU 25

__global__ __launch_bounds__(NTHREADS, 1)
void local_energy_kernel(const float* __restrict__ feats,
                         const float* __restrict__ bond_type,
                         const float* __restrict__ angle_type,
                         const float* __restrict__ tor_type,
                         const int*   __restrict__ multiplicity,
                         const float* __restrict__ opt_pars,
                         float* __restrict__ out)
{
    extern __shared__ char smem[];
    float4*         sc4   = (float4*)(smem + OFF_SC4);
    float*          stg   = (float*) (smem + OFF_STAGE);
    unsigned short* sb16  = (unsigned short*)(smem + OFF_SB16);
    unsigned short* sa16  = (unsigned short*)(smem + OFF_SA16);
    unsigned short* sg16  = (unsigned short*)(smem + OFF_SG16);
    float*          sbt   = (float*)(smem + OFF_TBL);
    float*          sat   = sbt + SM_BT;
    float*          stt   = sat + SM_AT;
    float*          smu   = stt + SM_TT;
    float*          sred  = smu + SM_MU;     /* 96 floats */

    const int b   = blockIdx.x;
    const int tid = threadIdx.x;

    const size_t gbase = (size_t)b * TOT_F;
    const int    aoff  = (int)(gbase & 3);            /* floats of misalignment */
    const float* abase = feats + (gbase - aoff);      /* 16B-aligned, <= slab start */
    const size_t total_f = (size_t)NBATCH * TOT_F;

    /* small tables (before first sync) */
    if (tid < SM_BT) sbt[tid] = bond_type[tid];
    else if (tid < SM_BT + SM_AT) sat[tid - SM_BT] = angle_type[tid - SM_BT];
    else if (tid < SM_BT + SM_AT + SM_TT) stt[tid - SM_BT - SM_AT] = tor_type[tid - SM_BT - SM_AT];
    else if (tid < SM_BT + SM_AT + SM_TT + SM_MU)
        smu[tid - SM_BT - SM_AT - SM_TT] = (float)multiplicity[tid - SM_BT - SM_AT - SM_TT];

    /* ---- staged, coalesced column extraction ---- */
    for (int t = 0; t < NTILES; t++) {
        const float* gsrc = abase + (size_t)t * TILE_F;   /* 16B aligned */
        /* floats needed in this tile (within slab) */
        int rem_f = TOT_F - t * TILE_F;
        if (rem_f > TILE_F) rem_f = TILE_F;
        int nv = (rem_f + aoff + 3) >> 2;                 /* float4 count */
        /* don't run past the whole features array */
        size_t gv0 = gbase - aoff + (size_t)t * TILE_F;   /* first float loaded */
        int nv_cap = (int)((total_f - gv0) >> 2);
        if (nv > nv_cap) nv = nv_cap;

        __syncthreads();   /* staging reuse: previous extraction done */
        const float4* gs4 = (const float4*)gsrc;
        float4*       st4 = (float4*)stg;
        for (int j = tid; j < nv; j += NTHREADS)
            st4[j] = gs4[j];
        __syncthreads();

        int r = t * TILE_ROWS + tid;
        if (r < MAX_LEN) {
            int base = ROW * tid + aoff;
            float c5 = stg[base + 5];
            float c6 = stg[base + 6];
            float c7 = stg[base + 7];
            float c8 = stg[base + 8];
            if (r < 3 * N_ATOMS) {
                int a    = r / 3;
                int comp = r - 3 * a;
                ((float*)sc4)[4 * a + comp] = c5;
            }
            if (r < 3 * NB) sb16[r] = (unsigned short)(int)c6;
            if (r < 4 * NA) sa16[r] = (unsigned short)(int)c7;
            sg16[r] = (unsigned short)(int)c8;
        }
    }
    __syncthreads();

    float eb = 0.0f, ea = 0.0f, et = 0.0f;

    /* ---------------- bonds ---------------- */
    for (int e = tid; e < NB; e += NTHREADS) {
        int i0 = sb16[3 * e + 0];
        int i1 = sb16[3 * e + 1];
        int ty = sb16[3 * e + 2];
        float4 p0 = sc4[i0];
        float4 p1 = sc4[i1];
        float dx = p0.x - p1.x, dy = p0.y - p1.y, dz = p0.z - p1.z;
        float r  = sqrtf(dx * dx + dy * dy + dz * dz + EPS);
        float dr = r - sbt[2 * ty + 1];
        eb += sbt[2 * ty + 0] * dr * dr;
    }

    /* ---------------- angles ---------------- */
    for (int e = tid; e < NA; e += NTHREADS) {
        int a0 = sa16[4 * e + 0];
        int a1 = sa16[4 * e + 1];
        int a2 = sa16[4 * e + 2];
        int ty = sa16[4 * e + 3];
        float4 p0 = sc4[a0];
        float4 p1 = sc4[a1];
        float4 p2 = sc4[a2];
        float v1x = p0.x - p1.x, v1y = p0.y - p1.y, v1z = p0.z - p1.z;
        float v2x = p2.x - p1.x, v2y = p2.y - p1.y, v2z = p2.z - p1.z;
        float d11 = v1x * v1x + v1y * v1y + v1z * v1z + EPS;
        float d22 = v2x * v2x + v2y * v2y + v2z * v2z + EPS;
        float d12 = v1x * v2x + v1y * v2y + v1z * v2z;
        float cosang = d12 / (sqrtf(d11) * sqrtf(d22));
        cosang = fminf(fmaxf(cosang, -1.0f + 1e-6f), 1.0f - 1e-6f);
        float theta = acosf(cosang);
        float dt = theta - sat[2 * ty + 1];
        ea += sat[2 * ty + 0] * dt * dt;
    }

    /* ---------------- torsions ---------------- */
    for (int e = tid; e < NT; e += NTHREADS) {
        int ti = sg16[5 * e + 0];
        int tj = sg16[5 * e + 1];
        int tk = sg16[5 * e + 2];
        int tl = sg16[5 * e + 3];
        int ty = sg16[5 * e + 4];
        float4 pi = sc4[ti];
        float4 pj = sc4[tj];
        float4 pk = sc4[tk];
        float4 pl = sc4[tl];

        float b1x = pj.x - pi.x, b1y = pj.y - pi.y, b1z = pj.z - pi.z;
        float b2x = pk.x - pj.x, b2y = pk.y - pj.y, b2z = pk.z - pj.z;
        float b3x = pl.x - pk.x, b3y = pl.y - pk.y, b3z = pl.z - pk.z;

        float n1x = b1y * b2z - b1z * b2y;
        float n1y = b1z * b2x - b1x * b2z;
        float n1z = b1x * b2y - b1y * b2x;
        float n2x = b2y * b3z - b2z * b3y;
        float n2y = b2z * b3x - b2x * b3z;
        float n2z = b2x * b3y - b2y * b3x;

        float inv = 1.0f / sqrtf(b2x * b2x + b2y * b2y + b2z * b2z + EPS);
        float bnx = b2x * inv, bny = b2y * inv, bnz = b2z * inv;

        float m1x = n1y * bnz - n1z * bny;
        float m1y = n1z * bnx - n1x * bnz;
        float m1z = n1x * bny - n1y * bnx;

        float y = m1x * n2x + m1y * n2y + m1z * n2z;
        float x = n1x * n2x + n1y * n2y + n1z * n2z;
        float phi = atan2f(y, x);

        et += stt[2 * ty + 0] * (1.0f + cosf(smu[ty] * phi - stt[2 * ty + 1]));
    }

    /* ---------------- block reduction ---------------- */
    const unsigned FULL = 0xFFFFFFFFu;
    #pragma unroll
    for (int off = 16; off > 0; off >>= 1) {
        eb += __shfl_down_sync(FULL, eb, off);
        ea += __shfl_down_sync(FULL, ea, off);
        et += __shfl_down_sync(FULL, et, off);
    }
    int warp = tid >> 5;
    int lane = tid & 31;
    if (lane == 0) {
        sred[warp]      = eb;
        sred[32 + warp] = ea;
        sred[64 + warp] = et;
    }
    __syncthreads();
    if (warp == 0) {
        float vb = sred[lane];
        float va = sred[32 + lane];
        float vt = sred[64 + lane];
        #pragma unroll
        for (int off = 16; off > 0; off >>= 1) {
            vb += __shfl_down_sync(FULL, vb, off);
            va += __shfl_down_sync(FULL, va, off);
            vt += __shfl_down_sync(FULL, vt, off);
        }
        if (lane == 0) {
            out[3 * b + 0] = opt_pars[0] * vb;
            out[3 * b + 1] = opt_pars[1] * va;
            out[3 * b + 2] = opt_pars[2] * vt;
        }
    }
}

extern "C" void kernel_launch(void* const* d_in, const int* in_sizes, int n_in,
                              void* d_out, int out_size)
{
    const float* feats      = (const float*)d_in[0];
    /* d_in[1] = lengths (unused by reference) */
    const float* bond_type  = (const float*)d_in[2];
    const float* angle_type = (const float*)d_in[3];
    const float* tor_type   = (const float*)d_in[4];
    const int*   mult       = (const int*)  d_in[5];
    const float* opt_pars   = (const float*)d_in[6];
    float*       out        = (float*)d_out;

    cudaFuncSetAttribute(local_energy_kernel,
                         cudaFuncAttributeMaxDynamicSharedMemorySize, SMEM_BYTES);

    local_energy_kernel<<<NBATCH, NTHREADS, SMEM_BYTES>>>(
        feats, bond_type, angle_type, tor_type, mult, opt_pars, out);
}

// round 5
// speedup vs baseline: 1.0692x; 1.0318x over previous
#include <cuda_runtime.h>
#include <math.h>

#define NBATCH   128
#define N_ATOMS  4096
#define NB       4095
#define NA       4094
#define NT       4093
#define MAX_LEN  (5 * NT)            /* 20465 rows */
#define ROW      9
#define TOT_F    (MAX_LEN * ROW)     /* 184185 floats per sample */
#define EPS      1e-8f

#define NTHREADS  1024
#define TILE_ROWS 768
#define TILE_F    (TILE_ROWS * ROW)  /* 6912 */
#define NTILES    27                 /* ceil(20465/768) */
#define BUF_FLOATS 6916              /* TILE_F + 4 (alignment slack) */

/* ---- shared memory layout (bytes) ---- */
#define OFF_SC4   0                              /* float4 coords[4096]   65536 */
#define OFF_BUF   65536                          /* 2 staging bufs        55328 */
#define OFF_SB16  (OFF_BUF + 2 * BUF_FLOATS * 4) /* 120864: u16[12288]    24576 */
#define OFF_SA16  (OFF_SB16 + 24576)             /* 145440: u16[16376]    32752 */
#define OFF_SG16  (OFF_SA16 + 32752)             /* 178192: u16[20466]    40932 */
#define OFF_TBL   219136                         /* padded, 16B aligned */
#define SMEM_BYTES 220160

/* table float indices (relative to OFF_TBL) */
#define T_SBT  0     /* bond_type   [30] */
#define T_SAT  30    /* angle_type  [26] */
#define T_TTK  56    /* torsion k   [25] */
#define T_TTC  81    /* cos(p0)     [25] */
#define T_TTS  106   /* sin(p0)     [25] */
#define T_TTN  131   /* multiplicity[25] */
#define T_RED  156   /* reduction   [96] */

__device__ __forceinline__ void cp_async16(unsigned int saddr, const void* gaddr) {
    asm volatile("cp.async.cg.shared.global [%0], [%1], 16;" :: "r"(saddr), "l"(gaddr));
}

__global__ __launch_bounds__(NTHREADS, 1)
void local_energy_kernel(const float* __restrict__ feats,
                         const float* __restrict__ bond_type,
                         const float* __restrict__ angle_type,
                         const float* __restrict__ tor_type,
                         const int*   __restrict__ multiplicity,
                         const float* __restrict__ opt_pars,
                         float* __restrict__ out)
{
    extern __shared__ char smem[];
    float4*         sc4  = (float4*)(smem + OFF_SC4);
    unsigned short* sb16 = (unsigned short*)(smem + OFF_SB16);
    unsigned short* sa16 = (unsigned short*)(smem + OFF_SA16);
    unsigned short* sg16 = (unsigned short*)(smem + OFF_SG16);
    float*          tbl  = (float*)(smem + OFF_TBL);

    const int b   = blockIdx.x;
    const int tid = threadIdx.x;

    const size_t gbase = (size_t)b * TOT_F;
    const int    aoff  = (int)(gbase & 3);
    const float* abase = feats + (gbase - aoff);   /* 16B aligned */

    /* ---- small tables (no sync needed yet; first use is long after syncs) */
    if (tid < 30) tbl[T_SBT + tid] = bond_type[tid];
    else if (tid < 56) tbl[T_SAT + (tid - 30)] = angle_type[tid - 30];
    else if (tid < 81) {
        int t = tid - 56;
        tbl[T_TTK + t] = tor_type[2 * t];
        float p = tor_type[2 * t + 1];
        tbl[T_TTC + t] = cosf(p);
        tbl[T_TTS + t] = sinf(p);
        tbl[T_TTN + t] = (float)multiplicity[t];
    }

    const unsigned int buf_s0 = (unsigned int)__cvta_generic_to_shared(smem + OFF_BUF);

    /* issue one tile's async copies (every thread commits a group) */
    auto issue_tile = [&](int t) {
        int rem = TOT_F - t * TILE_F;
        if (rem > TILE_F) rem = TILE_F;
        int nv4 = (rem + aoff + 3) >> 2;
        const float4* src = (const float4*)(abase + (size_t)t * TILE_F);
        unsigned int dst = buf_s0 + (unsigned int)(t & 1) * (BUF_FLOATS * 4);
        for (int j = tid; j < nv4; j += NTHREADS)
            cp_async16(dst + 16u * j, src + j);
        asm volatile("cp.async.commit_group;");
    };

    float eb = 0.0f, ea = 0.0f, et = 0.0f;

    issue_tile(0);
    issue_tile(1);

    for (int t = 0; t < NTILES; t++) {
        if (t + 1 < NTILES) asm volatile("cp.async.wait_group 1;");
        else                asm volatile("cp.async.wait_group 0;");
        __syncthreads();

        /* extract columns from staged tile t */
        {
            const float* stg = (const float*)(smem + OFF_BUF + (t & 1) * (BUF_FLOATS * 4));
            int r = t * TILE_ROWS + tid;
            if (tid < TILE_ROWS && r < MAX_LEN) {
                int base = ROW * tid + aoff;
                float c5 = stg[base + 5];
                float c6 = stg[base + 6];
                float c7 = stg[base + 7];
                float c8 = stg[base + 8];
                if (r < 3 * N_ATOMS) {
                    int a    = r / 3;
                    int comp = r - 3 * a;
                    ((float*)sc4)[4 * a + comp] = c5;
                }
                if (r < 3 * NB) sb16[r] = (unsigned short)(int)c6;
                if (r < 4 * NA) sa16[r] = (unsigned short)(int)c7;
                sg16[r] = (unsigned short)(int)c8;
            }
        }
        __syncthreads();

        if (t + 2 < NTILES) issue_tile(t + 2);

        /* ---- bonds: ready once tiles 0..15 extracted (rows < 12288) ---- */
        if (t == 15) {
            for (int e = tid; e < NB; e += NTHREADS) {
                int i0 = sb16[3 * e + 0];
                int i1 = sb16[3 * e + 1];
                int ty = sb16[3 * e + 2];
                float4 p0 = sc4[i0];
                float4 p1 = sc4[i1];
                float dx = p0.x - p1.x, dy = p0.y - p1.y, dz = p0.z - p1.z;
                float r  = sqrtf(dx * dx + dy * dy + dz * dz + EPS);
                float dr = r - tbl[T_SBT + 2 * ty + 1];
                eb += tbl[T_SBT + 2 * ty] * dr * dr;
            }
        }

        /* ---- angles: ready once tiles 0..21 extracted (rows < 16896) ---- */
        if (t == 21) {
            for (int e = tid; e < NA; e += NTHREADS) {
                int a0 = sa16[4 * e + 0];
                int a1 = sa16[4 * e + 1];
                int a2 = sa16[4 * e + 2];
                int ty = sa16[4 * e + 3];
                float4 p0 = sc4[a0];
                float4 p1 = sc4[a1];
                float4 p2 = sc4[a2];
                float v1x = p0.x - p1.x, v1y = p0.y - p1.y, v1z = p0.z - p1.z;
                float v2x = p2.x - p1.x, v2y = p2.y - p1.y, v2z = p2.z - p1.z;
                float d11 = v1x * v1x + v1y * v1y + v1z * v1z + EPS;
                float d22 = v2x * v2x + v2y * v2y + v2z * v2z + EPS;
                float d12 = v1x * v2x + v1y * v2y + v1z * v2z;
                float cosang = d12 * rsqrtf(d11 * d22);
                cosang = fminf(fmaxf(cosang, -1.0f + 1e-6f), 1.0f - 1e-6f);
                float theta = acosf(cosang);
                float dt = theta - tbl[T_SAT + 2 * ty + 1];
                ea += tbl[T_SAT + 2 * ty] * dt * dt;
            }
        }
    }

    /* ---------------- torsions (no atan2/cos: analytic cos(n*phi - p)) ------- */
    for (int e = tid; e < NT; e += NTHREADS) {
        int ti = sg16[5 * e + 0];
        int tj = sg16[5 * e + 1];
        int tk = sg16[5 * e + 2];
        int tl = sg16[5 * e + 3];
        int ty = sg16[5 * e + 4];
        float4 pi = sc4[ti];
        float4 pj = sc4[tj];
        float4 pk = sc4[tk];
        float4 pl = sc4[tl];

        float b1x = pj.x - pi.x, b1y = pj.y - pi.y, b1z = pj.z - pi.z;
        float b2x = pk.x - pj.x, b2y = pk.y - pj.y, b2z = pk.z - pj.z;
        float b3x = pl.x - pk.x, b3y = pl.y - pk.y, b3z = pl.z - pk.z;

        float n1x = b1y * b2z - b1z * b2y;
        float n1y = b1z * b2x - b1x * b2z;
        float n1z = b1x * b2y - b1y * b2x;
        float n2x = b2y * b3z - b2z * b3y;
        float n2y = b2z * b3x - b2x * b3z;
        float n2z = b2x * b3y - b2y * b3x;

        float L2 = b2x * b2x + b2y * b2y + b2z * b2z + EPS;   /* |b2|^2 + eps */
        float x  = n1x * n2x + n1y * n2y + n1z * n2z;

        /* m = n1 x b2 (unnormalized);  ym = m . n2 */
        float mx = n1y * b2z - n1z * b2y;
        float my = n1z * b2x - n1x * b2z;
        float mz = n1x * b2y - n1y * b2x;
        float ym = mx * n2x + my * n2y + mz * n2z;

        /* phi = atan2(ym / L, x):  cos = x*L/h, sin = ym/h, h = sqrt(x^2 L^2 + ym^2) */
        float u   = x * x * L2 + ym * ym;
        float inv = rsqrtf(fmaxf(u, 1e-38f));
        float L   = sqrtf(L2);
        float c   = x * L * inv;
        float s   = ym * inv;

        float nf = tbl[T_TTN + ty];
        float cn = c, sn = s;
        if (nf > 1.5f) {                    /* n >= 2 */
            cn = 2.0f * c * c - 1.0f;
            sn = 2.0f * s * c;
        }
        if (nf > 2.5f) {                    /* n == 3: (c3,s3) from (c2,s2) */
            float c3 = cn * c - sn * s;
            float s3 = sn * c + cn * s;
            cn = c3; sn = s3;
        }
        /* cos(n*phi - p) = cos(n phi) cos p + sin(n phi) sin p */
        et += tbl[T_TTK + ty] * (1.0f + cn * tbl[T_TTC + ty] + sn * tbl[T_TTS + ty]);
    }

    /* ---------------- block reduction ---------------- */
    float* sred = tbl + T_RED;
    const unsigned FULL = 0xFFFFFFFFu;
    #pragma unroll
    for (int off = 16; off > 0; off >>= 1) {
        eb += __shfl_down_sync(FULL, eb, off);
        ea += __shfl_down_sync(FULL, ea, off);
        et += __shfl_down_sync(FULL, et, off);
    }
    int warp = tid >> 5;
    int lane = tid & 31;
    if (lane == 0) {
        sred[warp]      = eb;
        sred[32 + warp] = ea;
        sred[64 + warp] = et;
    }
    __syncthreads();
    if (warp == 0) {
        float vb = sred[lane];
        float va = sred[32 + lane];
        float vt = sred[64 + lane];
        #pragma unroll
        for (int off = 16; off > 0; off >>= 1) {
            vb += __shfl_down_sync(FULL, vb, off);
            va += __shfl_down_sync(FULL, va, off);
            vt += __shfl_down_sync(FULL, vt, off);
        }
        if (lane == 0) {
            out[3 * b + 0] = opt_pars[0] * vb;
            out[3 * b + 1] = opt_pars[1] * va;
            out[3 * b + 2] = opt_pars[2] * vt;
        }
    }
}

extern "C" void kernel_launch(void* const* d_in, const int* in_sizes, int n_in,
                              void* d_out, int out_size)
{
    const float* feats      = (const float*)d_in[0];
    /* d_in[1] = lengths (unused by reference) */
    const float* bond_type  = (const float*)d_in[2];
    const float* angle_type = (const float*)d_in[3];
    const float* tor_type   = (const float*)d_in[4];
    const int*   mult       = (const int*)  d_in[5];
    const float* opt_pars   = (const float*)d_in[6];
    float*       out        = (float*)d_out;

    cudaFuncSetAttribute(local_energy_kernel,
                         cudaFuncAttributeMaxDynamicSharedMemorySize, SMEM_BYTES);

    local_energy_kernel<<<NBATCH, NTHREADS, SMEM_BYTES>>>(
        feats, bond_type, angle_type, tor_type, mult, opt_pars, out);
}